// round 7
// baseline (speedup 1.0000x reference)
#include <cuda_runtime.h>
#include <cuda_bf16.h>
#include <stdint.h>
#include <math.h>

#define NN   200000
#define NPL  12500
#define NLVL 16
#define DEG  8
#define HD   128
#define G3   384
#define EPL  (NPL*DEG)

#define APITCH 272        // bytes per bf16 A-tile row (128 bf16 + 8 pad)

#define LV_TM  16
#define LV_NT  256
#define LV_NCTA ((NPL + LV_TM - 1) / LV_TM)   // 782

__device__ float    g_x[(size_t)NN*HD];
__device__ float    g_h[(size_t)NN*HD];
__device__ uint32_t g_bfrag[196608];   // [layer][g][part][kt(8)][nb(48)][lane(32)][j(2)]

// ---------------- helpers ----------------
__device__ __forceinline__ uint32_t smem_u32(const void* p){
    uint32_t a;
    asm("{ .reg .u64 t; cvta.to.shared.u64 t, %1; cvt.u32.u64 %0, t; }" : "=r"(a) : "l"(p));
    return a;
}
__device__ __forceinline__ void ldsm4(uint32_t* a, uint32_t addr){
    asm volatile("ldmatrix.sync.aligned.m8n8.x4.shared.b16 {%0,%1,%2,%3}, [%4];"
        : "=r"(a[0]), "=r"(a[1]), "=r"(a[2]), "=r"(a[3]) : "r"(addr));
}
__device__ __forceinline__ void mma_bf16(float* d, const uint32_t* a, uint32_t b0, uint32_t b1){
    asm volatile("mma.sync.aligned.m16n8k16.row.col.f32.bf16.bf16.f32 "
        "{%0,%1,%2,%3}, {%4,%5,%6,%7}, {%8,%9}, {%0,%1,%2,%3};"
        : "+f"(d[0]), "+f"(d[1]), "+f"(d[2]), "+f"(d[3])
        : "r"(a[0]), "r"(a[1]), "r"(a[2]), "r"(a[3]), "r"(b0), "r"(b1));
}
__device__ __forceinline__ float sigmf(float v){ return 1.f / (1.f + __expf(-v)); }
__device__ __forceinline__ float tanhfast(float v){ return 2.f / (1.f + __expf(-2.f * v)) - 1.f; }
__device__ __forceinline__ float bflo(uint32_t u){ return __bfloat162float(__ushort_as_bfloat16((unsigned short)(u & 0xFFFF))); }
__device__ __forceinline__ float bfhi(uint32_t u){ return __bfloat162float(__ushort_as_bfloat16((unsigned short)(u >> 16))); }

// split 8 f32 -> hi/lo bf16, store as uint4 at padded (r, k0)
__device__ __forceinline__ void pack8(char* hi, char* lo, int r, int k0, float4 a, float4 b){
    float v[8] = {a.x, a.y, a.z, a.w, b.x, b.y, b.z, b.w};
    unsigned short hs[8], ls[8];
#pragma unroll
    for (int j = 0; j < 8; j++){
        __nv_bfloat16 h = __float2bfloat16(v[j]);
        __nv_bfloat16 l = __float2bfloat16(v[j] - __bfloat162float(h));
        hs[j] = __bfloat16_as_ushort(h);
        ls[j] = __bfloat16_as_ushort(l);
    }
    uint4 H, L;
    H.x = (uint32_t)hs[0] | ((uint32_t)hs[1] << 16);
    H.y = (uint32_t)hs[2] | ((uint32_t)hs[3] << 16);
    H.z = (uint32_t)hs[4] | ((uint32_t)hs[5] << 16);
    H.w = (uint32_t)hs[6] | ((uint32_t)hs[7] << 16);
    L.x = (uint32_t)ls[0] | ((uint32_t)ls[1] << 16);
    L.y = (uint32_t)ls[2] | ((uint32_t)ls[3] << 16);
    L.z = (uint32_t)ls[4] | ((uint32_t)ls[5] << 16);
    L.w = (uint32_t)ls[6] | ((uint32_t)ls[7] << 16);
    uint32_t o = (uint32_t)r * APITCH + (uint32_t)k0 * 2;
    *(uint4*)(hi + o) = H;
    *(uint4*)(lo + o) = L;
}

// ---------------- prep: weights -> bf16 hi/lo HMMA fragment arrays ----------------
__global__ void k_prep(const float* __restrict__ wx, const float* __restrict__ wh){
    int id = blockIdx.x * blockDim.x + threadIdx.x;
    if (id >= 196608) return;
    int pidx = id / 24576;                 // [layer(2)][g(2)][part(2)]
    int layer = pidx >> 2, g = (pidx >> 1) & 1, part = pidx & 1;
    int w = id % 24576;
    int kt = w / 3072;
    int rem = w % 3072;
    int nb = rem / 64;
    int rem2 = rem % 64;
    int lane = rem2 >> 1, j = rem2 & 1;
    int k = kt * 16 + (lane & 3) * 2 + 8 * j;
    int n = nb * 8 + (lane >> 2);
    const float* W = (g ? wh : wx) + (size_t)layer * HD * G3;
    float v0 = W[(size_t)k * G3 + n];
    float v1 = W[(size_t)(k + 1) * G3 + n];
    unsigned short p0, p1;
    __nv_bfloat16 h0 = __float2bfloat16(v0), h1 = __float2bfloat16(v1);
    if (part == 0){ p0 = __bfloat16_as_ushort(h0); p1 = __bfloat16_as_ushort(h1); }
    else {
        p0 = __bfloat16_as_ushort(__float2bfloat16(v0 - __bfloat162float(h0)));
        p1 = __bfloat16_as_ushort(__float2bfloat16(v1 - __bfloat162float(h1)));
    }
    g_bfrag[id] = (uint32_t)p0 | ((uint32_t)p1 << 16);
}

// ---------------- x = zeros.at[index_map].add(features): permutation -> plain store ----
__global__ void k_scatter4(const float4* __restrict__ f, const int* __restrict__ imap){
    int i = blockIdx.x * blockDim.x + threadIdx.x;
    if (i < NN * 32){
        int node = i >> 5, q = i & 31;
        *(float4*)(g_x + (size_t)__ldg(&imap[node]) * HD + q * 4) = f[i];
    }
}

// ---------------- fused level kernel: x-GEMM + gather mean + m-GEMM + GRU ----------------
__global__ void __launch_bounds__(LV_NT, 4) k_lv(
    const float* __restrict__ xsrc,
    float* __restrict__ hdst,
    const int* __restrict__ esrc,
    const float* __restrict__ bias,
    int layer, int lvl)
{
    __shared__ int   se[LV_TM * DEG];        // 512 B
    __shared__ float sb[G3];                 // 1.5 KB
    __shared__ char  sXH[LV_TM * APITCH];    // 4352 B
    __shared__ char  sXL[LV_TM * APITCH];
    __shared__ char  sMH[LV_TM * APITCH];
    __shared__ char  sML[LV_TM * APITCH];

    const int tid = threadIdx.x, warp = tid >> 5, lane = tid & 31;
    const int row0 = blockIdx.x * LV_TM;
    const int s = lvl * NPL;
    const bool hasM = (lvl > 0);

    if (hasM && tid < LV_TM * DEG){
        int r = tid >> 3;
        int rr = (row0 + r < NPL) ? (row0 + r) : (NPL - 1);
        se[tid] = __ldg(&esrc[(size_t)(lvl - 1) * EPL + rr * DEG + (tid & 7)]);
    }
    if (tid < G3 / 2) *(float2*)(sb + tid * 2) = *(const float2*)(bias + tid * 2);

    // pack x A-tile (one task per thread; independent of edges -> before sync)
    {
        int r = tid >> 4, k0 = (tid & 15) * 8;
        int node = s + ((row0 + r < NPL) ? (row0 + r) : (NPL - 1));
        const float4* p = (const float4*)(xsrc + (size_t)node * HD + k0);
        pack8(sXH, sXL, r, k0, p[0], p[1]);
    }
    __syncthreads();

    // gather mean -> pack m A-tile (one task per thread)
    if (hasM){
        int r = tid >> 4, k0 = (tid & 15) * 8;
        float4 s0 = make_float4(0.f, 0.f, 0.f, 0.f);
        float4 s1 = make_float4(0.f, 0.f, 0.f, 0.f);
#pragma unroll
        for (int e = 0; e < DEG; e++){
            const float4* p = (const float4*)(hdst + (size_t)se[r * DEG + e] * HD + k0);
            float4 v0 = p[0], v1 = p[1];
            s0.x += v0.x; s0.y += v0.y; s0.z += v0.z; s0.w += v0.w;
            s1.x += v1.x; s1.y += v1.y; s1.z += v1.z; s1.w += v1.w;
        }
        s0.x *= 0.125f; s0.y *= 0.125f; s0.z *= 0.125f; s0.w *= 0.125f;
        s1.x *= 0.125f; s1.y *= 0.125f; s1.z *= 0.125f; s1.w *= 0.125f;
        pack8(sMH, sML, r, k0, s0, s1);
    }
    __syncthreads();

    const uint32_t xH = smem_u32(sXH), xL = smem_u32(sXL);
    const uint32_t mH = smem_u32(sMH), mL = smem_u32(sML);
    const uint32_t laneOff = (uint32_t)(lane & 15) * APITCH + (uint32_t)((lane >> 4) << 4);
    const uint32_t* Bx_hi = g_bfrag + (size_t)((layer * 2 + 0) * 2 + 0) * 24576;
    const uint32_t* Bx_lo = g_bfrag + (size_t)((layer * 2 + 0) * 2 + 1) * 24576;
    const uint32_t* Bh_hi = g_bfrag + (size_t)((layer * 2 + 1) * 2 + 0) * 24576;
    const uint32_t* Bh_lo = g_bfrag + (size_t)((layer * 2 + 1) * 2 + 1) * 24576;

#pragma unroll
    for (int j = 0; j < 2; j++){
        // acc gates: 0 = r (Cx+Ch), 1 = z (Cx+Ch), 2 = n_x, 3 = n_h
        float acc[4][4];
#pragma unroll
        for (int g = 0; g < 4; g++)
#pragma unroll
            for (int q = 0; q < 4; q++) acc[g][q] = 0.f;

        const int nbBase = 2 * warp + j;
#pragma unroll 2
        for (int kt = 0; kt < 8; kt++){
            const size_t bb = (size_t)kt * 3072 + (size_t)lane * 2;
            const uint32_t ao = laneOff + (uint32_t)kt * 32;
            // x pass
            {
                uint2 BH[3], BL[3];
#pragma unroll
                for (int g = 0; g < 3; g++){
                    size_t idx = bb + (size_t)(16 * g + nbBase) * 64;
                    BH[g] = *(const uint2*)(Bx_hi + idx);
                    BL[g] = *(const uint2*)(Bx_lo + idx);
                }
                uint32_t ah[4], al[4];
                ldsm4(ah, xH + ao);
                ldsm4(al, xL + ao);
#pragma unroll
                for (int g = 0; g < 3; g++){
                    mma_bf16(acc[g], ah, BH[g].x, BH[g].y);
                    mma_bf16(acc[g], al, BH[g].x, BH[g].y);
                    mma_bf16(acc[g], ah, BL[g].x, BL[g].y);
                }
            }
            // m pass
            if (hasM){
                uint2 BH[3], BL[3];
#pragma unroll
                for (int g = 0; g < 3; g++){
                    size_t idx = bb + (size_t)(16 * g + nbBase) * 64;
                    BH[g] = *(const uint2*)(Bh_hi + idx);
                    BL[g] = *(const uint2*)(Bh_lo + idx);
                }
                uint32_t ah[4], al[4];
                ldsm4(ah, mH + ao);
                ldsm4(al, mL + ao);
#pragma unroll
                for (int g = 0; g < 2; g++){
                    mma_bf16(acc[g], ah, BH[g].x, BH[g].y);
                    mma_bf16(acc[g], al, BH[g].x, BH[g].y);
                    mma_bf16(acc[g], ah, BL[g].x, BL[g].y);
                }
                mma_bf16(acc[3], ah, BH[2].x, BH[2].y);
                mma_bf16(acc[3], al, BH[2].x, BH[2].y);
                mma_bf16(acc[3], ah, BL[2].x, BL[2].y);
            }
        }

        // epilogue for this col-group
        const int c0 = warp * 16 + j * 8 + (lane & 3) * 2;
        const float br0 = sb[c0],       br1 = sb[c0 + 1];
        const float bz0 = sb[128 + c0], bz1 = sb[128 + c0 + 1];
        const float bn0 = sb[256 + c0], bn1 = sb[256 + c0 + 1];
#pragma unroll
        for (int half = 0; half < 2; half++){
            int row = (lane >> 2) + half * 8;
            int nl = row0 + row;
            if (nl < NPL){
                float mv0 = 0.f, mv1 = 0.f;
                if (hasM){
                    uint32_t o = (uint32_t)row * APITCH + (uint32_t)c0 * 2;
                    uint32_t Hm = *(const uint32_t*)(sMH + o);
                    uint32_t Lm = *(const uint32_t*)(sML + o);
                    mv0 = bflo(Hm) + bflo(Lm);
                    mv1 = bfhi(Hm) + bfhi(Lm);
                }
                int q0 = half * 2;
                float r0 = sigmf(acc[0][q0]     + br0);
                float r1 = sigmf(acc[0][q0 + 1] + br1);
                float z0 = sigmf(acc[1][q0]     + bz0);
                float z1 = sigmf(acc[1][q0 + 1] + bz1);
                float n0 = tanhfast(acc[2][q0]     + bn0 + r0 * acc[3][q0]);
                float n1 = tanhfast(acc[2][q0 + 1] + bn1 + r1 * acc[3][q0 + 1]);
                *(float2*)(hdst + (size_t)(s + nl) * HD + c0) =
                    make_float2((1.f - z0) * n0 + z0 * mv0,
                                (1.f - z1) * n1 + z1 * mv1);
            }
        }
    }
}

// ---------------- out = h[index_map] ----------------
__global__ void k_gather4(const int* __restrict__ imap, float4* __restrict__ out){
    int i = blockIdx.x * blockDim.x + threadIdx.x;
    if (i < NN * 32){
        int node = i >> 5, q = i & 31;
        out[i] = *(const float4*)(g_h + (size_t)__ldg(&imap[node]) * HD + q * 4);
    }
}

extern "C" void kernel_launch(void* const* d_in, const int* in_sizes, int n_in,
                              void* d_out, int out_size){
    const float* feats = (const float*)d_in[0];
    const float* wx    = (const float*)d_in[1];  // (256,1,384)
    const float* wh    = (const float*)d_in[2];  // (2,128,1,384)
    const float* bs    = (const float*)d_in[3];  // (2,1,384)
    const int*   esrc  = (const int*)  d_in[4];
    // d_in[5] edge_dst unused: dsts contiguous by construction (repeat, DEG=8)
    const int*   imap  = (const int*)  d_in[6];
    float*       out   = (float*)d_out;

    void *px, *ph;
    cudaGetSymbolAddress(&px, g_x);
    cudaGetSymbolAddress(&ph, g_h);

    const int EV = NN * 32;  // float4 elements
    k_prep<<<(196608 + 255) / 256, 256>>>(wx, wh);
    k_scatter4<<<(EV + 255) / 256, 256>>>((const float4*)feats, imap);

    for (int layer = 0; layer < 2; layer++){
        const float* xs = (layer == 0) ? (const float*)px : (const float*)ph;
        const float* b  = bs + (size_t)layer * G3;
        for (int lvl = 0; lvl < NLVL; lvl++)
            k_lv<<<LV_NCTA, LV_NT>>>(xs, (float*)ph, esrc, b, layer, lvl);
    }

    k_gather4<<<(EV + 255) / 256, 256>>>(imap, (float4*)out);
}